// round 10
// baseline (speedup 1.0000x reference)
#include <cuda_runtime.h>
#include <cuda_bf16.h>
#include <cstdint>

#define TLEN 128
#define HID  256
#define CTXD 16

#define SBW 280                 // B row stride (bf16 units)
#define SBB 560                 // B row stride (bytes)
#define BSPL 73920              // one B split: 132 rows * 560B
#define A_OFF  147840           // A ring: 3 x 16KB
#define MB_OFF (A_OFF + 49152)  // full[3] @ +0/8/16, empty[3] @ +24/32/40
#define SCR_OFF (MB_OFF + 64)
#define CF_OFF  (SCR_OFF + 2048)
#define RV_OFF  (CF_OFF + 512)
#define RI_OFF  (RV_OFF + 64)
#define SMEM_BYTES (RI_OFF + 64)   // ~199.8 KB

#define NSTEP 320               // 64 proj + 8*32 conv steps, 16 k-units each
#define CHUNK 16384
__device__ __align__(1024) unsigned char gW[(size_t)NSTEP * CHUNK];

__device__ __forceinline__ void mma_bf16(float* d, uint32_t a0, uint32_t a1, uint32_t a2, uint32_t a3,
                                         uint32_t b0, uint32_t b1) {
    asm("mma.sync.aligned.m16n8k16.row.col.f32.bf16.bf16.f32 "
        "{%0,%1,%2,%3}, {%4,%5,%6,%7}, {%8,%9}, {%0,%1,%2,%3};"
        : "+f"(d[0]), "+f"(d[1]), "+f"(d[2]), "+f"(d[3])
        : "r"(a0), "r"(a1), "r"(a2), "r"(a3), "r"(b0), "r"(b1));
}
__device__ __forceinline__ void split2(float w, __nv_bfloat16& hi, __nv_bfloat16& lo) {
    hi = __float2bfloat16(w);
    lo = __float2bfloat16(w - __bfloat162float(hi));
}
__device__ __forceinline__ unsigned short spc(float w, int sp) {
    __nv_bfloat16 hi = __float2bfloat16(w);
    if (sp == 0) return __bfloat16_as_ushort(hi);
    return __bfloat16_as_ushort(__float2bfloat16(w - __bfloat162float(hi)));
}
__device__ __forceinline__ int PERMC(int k) {
    int v = k & 15, p = v >> 1, bb = v & 1;
    int pos = (p < 4) ? (p << 1) : (((p - 4) << 1) + 1);
    return (k & ~15) + (pos << 1) + bb;
}

// ---- mbarrier / bulk helpers (all base sm_90 forms; compiled OK in earlier rounds) ----
__device__ __forceinline__ void mb_init(uint32_t mb, uint32_t cnt) {
    asm volatile("mbarrier.init.shared.b64 [%0], %1;" :: "r"(mb), "r"(cnt) : "memory");
}
__device__ __forceinline__ void mb_arrive(uint32_t mb) {
    asm volatile("mbarrier.arrive.shared.b64 _, [%0];" :: "r"(mb) : "memory");
}
__device__ __forceinline__ void mb_expect(uint32_t mb, uint32_t bytes) {
    asm volatile("mbarrier.arrive.expect_tx.shared.b64 _, [%0], %1;" :: "r"(mb), "r"(bytes) : "memory");
}
__device__ __forceinline__ void mb_wait(uint32_t mb, uint32_t ph) {
    asm volatile("{\n\t.reg .pred P;\n\tLW%=:\n\tmbarrier.try_wait.parity.shared.b64 P, [%0], %1;\n\t@!P bra LW%=;\n\t}"
                 :: "r"(mb), "r"(ph) : "memory");
}
__device__ __forceinline__ void bulk_cp(uint32_t dst, const void* src, uint32_t bytes, uint32_t mb) {
    asm volatile("cp.async.bulk.shared::cluster.global.mbarrier::complete_tx::bytes [%0], [%1], %2, [%3];"
                 :: "r"(dst), "l"(src), "r"(bytes), "r"(mb) : "memory");
}

// ---------------- prep: weights -> per-lane fragment-order step images (unchanged from R9) ----------------
__global__ void prep_kernel(const float* __restrict__ conv_w, const float* __restrict__ proj_w) {
    const int gs = blockIdx.x, t = threadIdx.x;
    const int lane = t & 31, sp = (t >> 5) & 1, mgq = t >> 6;
    const int gr = lane >> 2, lc = lane & 3;
    int base, l = 0, tap = 0;
    bool proj;
    if (gs < 64) { proj = true; base = gs * 16; }
    else { int tt = gs - 64; l = tt >> 5; int c = tt & 31; tap = c >> 4; base = (c & 15) * 16; proj = false; }
    for (int mgi = 0; mgi < 4; mgi++) {
        int mg = mgq * 4 + mgi;
        int m0 = mg * 16 + gr, m1 = m0 + 8;
        int c0 = base + lc * 2, c2 = c0 + 8;
        float w[8];
        if (proj) {
            w[0] = proj_w[(size_t)m0 * 1024 + c0]; w[1] = proj_w[(size_t)m0 * 1024 + c0 + 1];
            w[2] = proj_w[(size_t)m1 * 1024 + c0]; w[3] = proj_w[(size_t)m1 * 1024 + c0 + 1];
            w[4] = proj_w[(size_t)m0 * 1024 + c2]; w[5] = proj_w[(size_t)m0 * 1024 + c2 + 1];
            w[6] = proj_w[(size_t)m1 * 1024 + c2]; w[7] = proj_w[(size_t)m1 * 1024 + c2 + 1];
        } else {
            const float* cw = conv_w + (size_t)l * 256 * 256 * 2 + tap;
            w[0] = cw[((size_t)m0 * 256 + c0) * 2]; w[1] = cw[((size_t)m0 * 256 + c0 + 1) * 2];
            w[2] = cw[((size_t)m1 * 256 + c0) * 2]; w[3] = cw[((size_t)m1 * 256 + c0 + 1) * 2];
            w[4] = cw[((size_t)m0 * 256 + c2) * 2]; w[5] = cw[((size_t)m0 * 256 + c2 + 1) * 2];
            w[6] = cw[((size_t)m1 * 256 + c2) * 2]; w[7] = cw[((size_t)m1 * 256 + c2 + 1) * 2];
        }
        uint32_t u[4];
        #pragma unroll
        for (int i = 0; i < 4; i++)
            u[i] = (uint32_t)spc(w[i * 2], sp) | ((uint32_t)spc(w[i * 2 + 1], sp) << 16);
        *(uint4*)(gW + ((size_t)(gs * 16 + mg) * 2 + sp) * 512 + lane * 16) =
            make_uint4(u[0], u[1], u[2], u[3]);
    }
}

// one 16-k step for a 64m x 32t warp tile
__device__ __forceinline__ void gemm16(
    float (&d)[4][4][4], const unsigned char* Bh, const unsigned char* Bl,
    const unsigned char* Afrag, const int* brow, int cb, int shiftB, int nv)
{
    uint4 ah[4], al[4];
    #pragma unroll
    for (int mi = 0; mi < 4; mi++) {
        ah[mi] = *(const uint4*)(Afrag + mi * 1024);
        al[mi] = *(const uint4*)(Afrag + mi * 1024 + 512);
    }
    uint2 bh[4], bl[4];
    #pragma unroll
    for (int ni = 0; ni < 4; ni++) {
        if (ni < nv) {
            int bb = brow[ni] + shiftB + cb;
            bh[ni] = *(const uint2*)(Bh + bb);
            bl[ni] = *(const uint2*)(Bl + bb);
        }
    }
    #pragma unroll
    for (int ni = 0; ni < 4; ni++)              // w_hi * h_hi
        if (ni < nv)
            #pragma unroll
            for (int mi = 0; mi < 4; mi++)
                mma_bf16(d[mi][ni], ah[mi].x, ah[mi].y, ah[mi].z, ah[mi].w, bh[ni].x, bh[ni].y);
    #pragma unroll
    for (int ni = 0; ni < 4; ni++)              // w_lo * h_hi
        if (ni < nv)
            #pragma unroll
            for (int mi = 0; mi < 4; mi++)
                mma_bf16(d[mi][ni], al[mi].x, al[mi].y, al[mi].z, al[mi].w, bh[ni].x, bh[ni].y);
    #pragma unroll
    for (int ni = 0; ni < 4; ni++)              // w_hi * h_lo
        if (ni < nv)
            #pragma unroll
            for (int mi = 0; mi < 4; mi++)
                mma_bf16(d[mi][ni], ah[mi].x, ah[mi].y, ah[mi].z, ah[mi].w, bl[ni].x, bl[ni].y);
}

// ---------------- main ----------------
__global__ __launch_bounds__(512, 1)
void Model_26147760898465_kernel(
    const float* __restrict__ x,
    const float* __restrict__ proj_b, const float* __restrict__ conv_b,
    const float* __restrict__ ev_w,  const float* __restrict__ ev_b,
    const float* __restrict__ sw_w,  const float* __restrict__ sw_b,
    float* __restrict__ out)
{
    extern __shared__ unsigned char sm[];
    __nv_bfloat16* Bhi = (__nv_bfloat16*)sm;
    __nv_bfloat16* Blo = (__nv_bfloat16*)(sm + BSPL);

    const int tid = threadIdx.x, warp = tid >> 5, lane = tid & 31;
    const int gr = lane >> 2, lc = lane & 3, b = blockIdx.x;
    const int mo = (warp & 3) * 64, to = (warp >> 2) * 32;
    const uint32_t sbase = (uint32_t)__cvta_generic_to_shared(sm);
    const uint32_t mbF = sbase + MB_OFF, mbE = sbase + MB_OFF + 24;
    const int pmb = 2 * (gr & ~1) + (gr & 1);

    int brow[4];
    #pragma unroll
    for (int ni = 0; ni < 4; ni++) brow[ni] = (to + ni * 8 + gr) * SBB;

    // pipeline init + prime steps 0..2
    if (tid == 0) {
        #pragma unroll
        for (int i = 0; i < 3; i++) { mb_init(mbF + i * 8, 1); mb_init(mbE + i * 8, 16); }
    }
    __syncthreads();
    if (tid == 0) {
        #pragma unroll
        for (int s = 0; s < 3; s++) {
            mb_expect(mbF + s * 8, CHUNK);
            bulk_cp(sbase + A_OFF + s * CHUNK, gW + (size_t)s * CHUNK, CHUNK, mbF + s * 8);
        }
    }

    // zero pad rows 128..131 of both B splits
    for (int i = tid; i < 4 * SBW; i += 512) {
        Bhi[128 * SBW + i] = __float2bfloat16(0.f);
        Blo[128 * SBW + i] = __float2bfloat16(0.f);
    }

    float d[4][4][4];
    #pragma unroll
    for (int mi = 0; mi < 4; mi++)
        #pragma unroll
        for (int ni = 0; ni < 4; ni++)
            #pragma unroll
            for (int r = 0; r < 4; r++) d[mi][ni][r] = 0.f;

    // ======== projection: 4 passes x 16 steps ========
    for (int p = 0; p < 4; p++) {
        __syncthreads();   // prev pass gemm reads done
        {   // build B (permuted pair positions) from x: 512 threads
            int cp = tid & 127, th = tid >> 7;           // th 0..3
            int p7 = cp & 7;
            int widx = (cp & ~7) + (p7 < 4 ? 2 * p7 : 2 * (p7 - 4) + 1);
            const float* xp0 = x + ((size_t)b * 1024 + p * 256 + cp * 2) * TLEN;
            const float* xp1 = xp0 + TLEN;
            for (int q = 0; q < 8; q++) {
                int t = th * 32 + q * 4;
                float4 v0 = *(const float4*)(xp0 + t);
                float4 v1 = *(const float4*)(xp1 + t);
                float a0[4] = {v0.x, v0.y, v0.z, v0.w};
                float a1[4] = {v1.x, v1.y, v1.z, v1.w};
                #pragma unroll
                for (int j = 0; j < 4; j++) {
                    __nv_bfloat16 h0, l0, h1, l1;
                    split2(a0[j], h0, l0); split2(a1[j], h1, l1);
                    ((uint32_t*)Bhi)[(t + j) * (SBW / 2) + widx] =
                        (uint32_t)__bfloat16_as_ushort(h0) | ((uint32_t)__bfloat16_as_ushort(h1) << 16);
                    ((uint32_t*)Blo)[(t + j) * (SBW / 2) + widx] =
                        (uint32_t)__bfloat16_as_ushort(l0) | ((uint32_t)__bfloat16_as_ushort(l1) << 16);
                }
            }
        }
        __syncthreads();
        for (int q = 0; q < 16; q++) {
            int s = p * 16 + q;
            int buf = s % 3; uint32_t ph = (uint32_t)(s / 3) & 1u;
            mb_wait(mbF + buf * 8, ph);
            const unsigned char* Ab = sm + A_OFF + buf * CHUNK + ((warp & 3) << 12) + (lane << 4);
            gemm16(d, sm, sm + BSPL, Ab, brow, q * 32 + lc * 8, 0, 4);
            if (lane == 0) mb_arrive(mbE + buf * 8);
            if (tid == 0 && s + 3 < NSTEP) {
                mb_wait(mbE + buf * 8, ph);
                mb_expect(mbF + buf * 8, CHUNK);
                bulk_cp(sbase + A_OFF + buf * CHUNK, gW + (size_t)(s + 3) * CHUNK, CHUNK, mbF + buf * 8);
            }
        }
    }
    __syncthreads();
    // proj epilogue: bias, write splits
    {
        float bias[4][2];
        #pragma unroll
        for (int mi = 0; mi < 4; mi++) {
            bias[mi][0] = __ldg(proj_b + mo + mi * 16 + gr);
            bias[mi][1] = __ldg(proj_b + mo + mi * 16 + gr + 8);
        }
        #pragma unroll
        for (int mi = 0; mi < 4; mi++)
            #pragma unroll
            for (int ni = 0; ni < 4; ni++)
                #pragma unroll
                for (int r = 0; r < 4; r++) {
                    int rb = r >> 1;
                    int ms = mo + mi * 16 + pmb + 2 * rb;
                    int t = to + ni * 8 + lc * 2 + (r & 1);
                    float y = d[mi][ni][r] + bias[mi][rb];
                    __nv_bfloat16 hi, lo; split2(y, hi, lo);
                    Bhi[t * SBW + ms] = hi; Blo[t * SBW + ms] = lo;
                }
        __syncthreads();
    }

    // ======== 8 conv layers: 32 steps each ========
    const int DILS[8] = {1, 2, 4, 8, 16, 32, 64, 1};
    for (int l = 0; l < 8; l++) {
        const int D = DILS[l];
        #pragma unroll
        for (int mi = 0; mi < 4; mi++)
            #pragma unroll
            for (int ni = 0; ni < 4; ni++)
                #pragma unroll
                for (int r = 0; r < 4; r++) d[mi][ni][r] = 0.f;

        for (int c = 0; c < 32; c++) {
            int s = 64 + l * 32 + c;
            int buf = s % 3; uint32_t ph = (uint32_t)(s / 3) & 1u;
            int tap = c >> 4, kb = c & 15;
            int shiftB = tap ? D * SBB : 0;
            int nv = 4;
            if (tap && D >= 8) { int nn = (128 - D - to) >> 3; nv = nn < 0 ? 0 : (nn > 4 ? 4 : nn); }
            mb_wait(mbF + buf * 8, ph);
            const unsigned char* Ab = sm + A_OFF + buf * CHUNK + ((warp & 3) << 12) + (lane << 4);
            gemm16(d, sm, sm + BSPL, Ab, brow, kb * 32 + lc * 8, shiftB, nv);
            if (lane == 0) mb_arrive(mbE + buf * 8);
            if (tid == 0 && s + 3 < NSTEP) {
                mb_wait(mbE + buf * 8, ph);
                mb_expect(mbF + buf * 8, CHUNK);
                bulk_cp(sbase + A_OFF + buf * CHUNK, gW + (size_t)(s + 3) * CHUNK, CHUNK, mbF + buf * 8);
            }
        }

        // epilogue: bias + leaky + skip + unit-norm
        float* scr = (float*)(sm + SCR_OFF);
        float* colfac = (float*)(sm + CF_OFF);
        float bias[4][2];
        #pragma unroll
        for (int mi = 0; mi < 4; mi++) {
            bias[mi][0] = __ldg(conv_b + l * HID + mo + mi * 16 + gr);
            bias[mi][1] = __ldg(conv_b + l * HID + mo + mi * 16 + gr + 8);
        }
        float ps[4][2];
        #pragma unroll
        for (int ni = 0; ni < 4; ni++) { ps[ni][0] = 0.f; ps[ni][1] = 0.f; }
        #pragma unroll
        for (int mi = 0; mi < 4; mi++)
            #pragma unroll
            for (int ni = 0; ni < 4; ni++)
                #pragma unroll
                for (int r = 0; r < 4; r++) {
                    int rb = r >> 1;
                    int ms = mo + mi * 16 + pmb + 2 * rb;
                    int t = to + ni * 8 + lc * 2 + (r & 1);
                    float y = d[mi][ni][r] + bias[mi][rb];
                    y = (y > 0.f) ? y : 0.2f * y;
                    y += __bfloat162float(Bhi[t * SBW + ms]) + __bfloat162float(Blo[t * SBW + ms]);
                    d[mi][ni][r] = y;
                    ps[ni][r & 1] = fmaf(y, y, ps[ni][r & 1]);
                }
        #pragma unroll
        for (int ni = 0; ni < 4; ni++)
            #pragma unroll
            for (int j = 0; j < 2; j++) {
                float v = ps[ni][j];
                v += __shfl_down_sync(0xffffffffu, v, 16);
                v += __shfl_down_sync(0xffffffffu, v, 8);
                v += __shfl_down_sync(0xffffffffu, v, 4);
                ps[ni][j] = v;
            }
        if (lane < 4) {
            #pragma unroll
            for (int ni = 0; ni < 4; ni++)
                #pragma unroll
                for (int j = 0; j < 2; j++)
                    scr[(warp & 3) * 128 + to + ni * 8 + lane * 2 + j] = ps[ni][j];
        }
        __syncthreads();
        if (tid < TLEN) {
            float s = scr[tid] + scr[128 + tid] + scr[256 + tid] + scr[384 + tid];
            colfac[tid] = 1.0f / (sqrtf(s) + 1e-8f);
        }
        __syncthreads();
        float cf[4][2];
        #pragma unroll
        for (int ni = 0; ni < 4; ni++) {
            cf[ni][0] = colfac[to + ni * 8 + lc * 2];
            cf[ni][1] = colfac[to + ni * 8 + lc * 2 + 1];
        }
        #pragma unroll
        for (int mi = 0; mi < 4; mi++)
            #pragma unroll
            for (int ni = 0; ni < 4; ni++)
                #pragma unroll
                for (int r = 0; r < 4; r++) {
                    int rb = r >> 1;
                    int ms = mo + mi * 16 + pmb + 2 * rb;
                    int t = to + ni * 8 + lc * 2 + (r & 1);
                    float y = d[mi][ni][r] * cf[ni][r & 1];
                    __nv_bfloat16 hi, lo; split2(y, hi, lo);
                    Bhi[t * SBW + ms] = hi; Blo[t * SBW + ms] = lo;
                }
        __syncthreads();
    }

    // ======== heads (pipeline fully drained) ========
    float* pa   = (float*)(sm + A_OFF);            // [2][17][128] partials
    float* evw  = (float*)(sm + A_OFF + 17408);    // 16x256 permuted
    float* sww  = evw + CTXD * HID;                // 256 permuted
    float* evs  = sww + HID;                       // 16x128
    float* attn = evs + CTXD * TLEN;               // 128
    float* redv = (float*)(sm + RV_OFF);
    int*   redi = (int*)(sm + RI_OFF);
    for (int i = tid; i < CTXD * HID; i += 512) {
        int cc = i >> 8, k = i & 255;
        evw[cc * HID + PERMC(k)] = __ldg(ev_w + i);
    }
    if (tid < 256) sww[PERMC(tid)] = __ldg(sw_w + tid);
    __syncthreads();
    if (tid < 256) {
        int t = tid >> 1, hf = tid & 1;
        float a[CTXD + 1];
        #pragma unroll
        for (int cc = 0; cc <= CTXD; cc++) a[cc] = 0.f;
        int i0 = hf * 128;
        for (int i = i0; i < i0 + 128; i++) {
            float hv = __bfloat162float(Bhi[t * SBW + i]) + __bfloat162float(Blo[t * SBW + i]);
            #pragma unroll
            for (int cc = 0; cc < CTXD; cc++) a[cc] = fmaf(evw[cc * HID + i], hv, a[cc]);
            a[CTXD] = fmaf(sww[i], hv, a[CTXD]);
        }
        #pragma unroll
        for (int cc = 0; cc <= CTXD; cc++) pa[(hf * 17 + cc) * 128 + t] = a[cc];
    }
    __syncthreads();
    if (tid < TLEN) {
        #pragma unroll
        for (int cc = 0; cc < CTXD; cc++)
            evs[cc * TLEN + tid] = pa[cc * 128 + tid] + pa[(17 + cc) * 128 + tid] + __ldg(ev_b + cc);
        float sw = pa[16 * 128 + tid] + pa[33 * 128 + tid] + __ldg(sw_b);
        attn[tid] = fmaxf(sw, 0.f);
    }
    __syncthreads();
    if (tid < TLEN) {
        float v = attn[tid]; int idx = tid;
        #pragma unroll
        for (int off = 16; off > 0; off >>= 1) {
            float ov = __shfl_down_sync(0xffffffffu, v, off);
            int   oi = __shfl_down_sync(0xffffffffu, idx, off);
            if (ov > v || (ov == v && oi < idx)) { v = ov; idx = oi; }
        }
        if (lane == 0) { redv[warp] = v; redi[warp] = idx; }
    }
    __syncthreads();
    if (tid == 0) {
        float v = redv[0]; int idx = redi[0];
        for (int w = 1; w < 4; w++)
            if (redv[w] > v || (redv[w] == v && redi[w] < idx)) { v = redv[w]; idx = redi[w]; }
        redv[0] = v; redi[0] = idx;
    }
    __syncthreads();
    const int bi = redi[0]; const float bv = redv[0];
    if (tid < CTXD) out[(size_t)b * CTXD + tid] = evs[tid * TLEN + bi];
    if (tid < TLEN) out[(size_t)gridDim.x * CTXD + (size_t)b * TLEN + tid] = (tid == bi) ? bv : 0.f;
}

extern "C" void kernel_launch(void* const* d_in, const int* in_sizes, int n_in,
                              void* d_out, int out_size)
{
    const float* x      = (const float*)d_in[0];
    const float* proj_w = (const float*)d_in[1];
    const float* proj_b = (const float*)d_in[2];
    const float* conv_w = (const float*)d_in[3];
    const float* conv_b = (const float*)d_in[4];
    const float* ev_w   = (const float*)d_in[5];
    const float* ev_b   = (const float*)d_in[6];
    const float* sw_w   = (const float*)d_in[7];
    const float* sw_b   = (const float*)d_in[8];
    float* out = (float*)d_out;
    const int B = in_sizes[0] / (1024 * TLEN);   // 256

    prep_kernel<<<NSTEP, 256>>>(conv_w, proj_w);
    cudaFuncSetAttribute(Model_26147760898465_kernel,
                         cudaFuncAttributeMaxDynamicSharedMemorySize, SMEM_BYTES);
    Model_26147760898465_kernel<<<B, 512, SMEM_BYTES>>>(
        x, proj_b, conv_b, ev_w, ev_b, sw_w, sw_b, out);
}

// round 11
// speedup vs baseline: 1.1789x; 1.1789x over previous
#include <cuda_runtime.h>
#include <cuda_bf16.h>
#include <cstdint>

#define TLEN 128
#define HID  256
#define CTXD 16

#define SBW 280                 // B row stride (bf16 units)
#define SBB 560                 // B row stride (bytes)
#define BSPL 73920              // one B split: 132 rows * 560B
#define A0_OFF 147840           // A buffer 0 (32 KB)
#define A1_OFF 180608           // A buffer 1 (32 KB)
#define SCR_OFF 213376          // [8][128] floats
#define CF_OFF  217472
#define RV_OFF  217984
#define RI_OFF  218048
#define SMEM_BYTES 218112

#define NSTEP 320               // 64 proj + 8*32 conv steps, 16 k-units each
__device__ __align__(1024) unsigned char gW[(size_t)NSTEP * 16384];

__device__ __forceinline__ void mma_bf16(float* d, uint32_t a0, uint32_t a1, uint32_t a2, uint32_t a3,
                                         uint32_t b0, uint32_t b1) {
    asm("mma.sync.aligned.m16n8k16.row.col.f32.bf16.bf16.f32 "
        "{%0,%1,%2,%3}, {%4,%5,%6,%7}, {%8,%9}, {%0,%1,%2,%3};"
        : "+f"(d[0]), "+f"(d[1]), "+f"(d[2]), "+f"(d[3])
        : "r"(a0), "r"(a1), "r"(a2), "r"(a3), "r"(b0), "r"(b1));
}
__device__ __forceinline__ void split2(float w, __nv_bfloat16& hi, __nv_bfloat16& lo) {
    hi = __float2bfloat16(w);
    lo = __float2bfloat16(w - __bfloat162float(hi));
}
__device__ __forceinline__ unsigned short spc(float w, int sp) {
    __nv_bfloat16 hi = __float2bfloat16(w);
    if (sp == 0) return __bfloat16_as_ushort(hi);
    return __bfloat16_as_ushort(__float2bfloat16(w - __bfloat162float(hi)));
}
__device__ __forceinline__ int PERMC(int k) {
    int v = k & 15, p = v >> 1, bb = v & 1;
    int pos = (p < 4) ? (p << 1) : (((p - 4) << 1) + 1);
    return (k & ~15) + (pos << 1) + bb;
}

// ---------------- prep: identical step-image layout to R9 ----------------
__global__ void prep_kernel(const float* __restrict__ conv_w, const float* __restrict__ proj_w) {
    const int gs = blockIdx.x, t = threadIdx.x;
    const int lane = t & 31, sp = (t >> 5) & 1, mgq = t >> 6;
    const int gr = lane >> 2, lc = lane & 3;
    int base, l = 0, tap = 0;
    bool proj;
    if (gs < 64) { proj = true; base = gs * 16; }
    else { int tt = gs - 64; l = tt >> 5; int c = tt & 31; tap = c >> 4; base = (c & 15) * 16; proj = false; }
    for (int mgi = 0; mgi < 4; mgi++) {
        int mg = mgq * 4 + mgi;
        int m0 = mg * 16 + gr, m1 = m0 + 8;
        int c0 = base + lc * 2, c2 = c0 + 8;
        float w[8];
        if (proj) {
            w[0] = proj_w[(size_t)m0 * 1024 + c0]; w[1] = proj_w[(size_t)m0 * 1024 + c0 + 1];
            w[2] = proj_w[(size_t)m1 * 1024 + c0]; w[3] = proj_w[(size_t)m1 * 1024 + c0 + 1];
            w[4] = proj_w[(size_t)m0 * 1024 + c2]; w[5] = proj_w[(size_t)m0 * 1024 + c2 + 1];
            w[6] = proj_w[(size_t)m1 * 1024 + c2]; w[7] = proj_w[(size_t)m1 * 1024 + c2 + 1];
        } else {
            const float* cw = conv_w + (size_t)l * 256 * 256 * 2 + tap;
            w[0] = cw[((size_t)m0 * 256 + c0) * 2]; w[1] = cw[((size_t)m0 * 256 + c0 + 1) * 2];
            w[2] = cw[((size_t)m1 * 256 + c0) * 2]; w[3] = cw[((size_t)m1 * 256 + c0 + 1) * 2];
            w[4] = cw[((size_t)m0 * 256 + c2) * 2]; w[5] = cw[((size_t)m0 * 256 + c2 + 1) * 2];
            w[6] = cw[((size_t)m1 * 256 + c2) * 2]; w[7] = cw[((size_t)m1 * 256 + c2 + 1) * 2];
        }
        uint32_t u[4];
        #pragma unroll
        for (int i = 0; i < 4; i++)
            u[i] = (uint32_t)spc(w[i * 2], sp) | ((uint32_t)spc(w[i * 2 + 1], sp) << 16);
        *(uint4*)(gW + ((size_t)(gs * 16 + mg) * 2 + sp) * 512 + lane * 16) =
            make_uint4(u[0], u[1], u[2], u[3]);
    }
}

// ---------------- pipeline helpers ----------------
__device__ __forceinline__ void wait1() { asm volatile("cp.async.wait_group 1;" ::: "memory"); }
__device__ __forceinline__ void wait0() { asm volatile("cp.async.wait_group 0;" ::: "memory"); }

// each warp copies its OWN 2KB slice (2 mg groups x 2 splits x 512B, contiguous in gW)
__device__ __forceinline__ void issue_step(uint32_t sbase, int s2, int mgpair, int warp, int lane) {
    uint32_t dst = sbase + ((s2 & 1) ? A1_OFF : A0_OFF) + (warp << 11) + (lane << 4);
    const unsigned char* src = gW + ((size_t)s2 * 32 + mgpair * 2) * 512 + lane * 16;
    #pragma unroll
    for (int q = 0; q < 4; q++)
        asm volatile("cp.async.cg.shared.global [%0], [%1], 16;"
                     :: "r"(dst + q * 512), "l"(src + q * 512));
    asm volatile("cp.async.commit_group;");
}

// one 16-k step for a 32m x 64t warp tile
__device__ __forceinline__ void gemm16(
    float (&d)[2][8][4], const unsigned char* Bh, const unsigned char* Bl,
    const unsigned char* Afrag, const int* brow, int cb, int shiftB, int nv)
{
    uint4 ah[2], al[2];
    #pragma unroll
    for (int mi = 0; mi < 2; mi++) {
        ah[mi] = *(const uint4*)(Afrag + mi * 1024);
        al[mi] = *(const uint4*)(Afrag + mi * 1024 + 512);
    }
    #pragma unroll
    for (int ih = 0; ih < 2; ih++) {
        uint2 bh[4], bl[4];
        #pragma unroll
        for (int nj = 0; nj < 4; nj++) {
            int ni = ih * 4 + nj;
            if (ni < nv) {
                int bb = brow[ni] + shiftB + cb;
                bh[nj] = *(const uint2*)(Bh + bb);
                bl[nj] = *(const uint2*)(Bl + bb);
            }
        }
        #pragma unroll
        for (int nj = 0; nj < 4; nj++) {            // w_hi * h_hi
            int ni = ih * 4 + nj;
            if (ni < nv)
                #pragma unroll
                for (int mi = 0; mi < 2; mi++)
                    mma_bf16(d[mi][ni], ah[mi].x, ah[mi].y, ah[mi].z, ah[mi].w, bh[nj].x, bh[nj].y);
        }
        #pragma unroll
        for (int nj = 0; nj < 4; nj++) {            // w_lo * h_hi
            int ni = ih * 4 + nj;
            if (ni < nv)
                #pragma unroll
                for (int mi = 0; mi < 2; mi++)
                    mma_bf16(d[mi][ni], al[mi].x, al[mi].y, al[mi].z, al[mi].w, bh[nj].x, bh[nj].y);
        }
        #pragma unroll
        for (int nj = 0; nj < 4; nj++) {            // w_hi * h_lo
            int ni = ih * 4 + nj;
            if (ni < nv)
                #pragma unroll
                for (int mi = 0; mi < 2; mi++)
                    mma_bf16(d[mi][ni], ah[mi].x, ah[mi].y, ah[mi].z, ah[mi].w, bl[nj].x, bl[nj].y);
        }
    }
}

// ---------------- main ----------------
__global__ __launch_bounds__(512, 1)
void Model_26147760898465_kernel(
    const float* __restrict__ x,
    const float* __restrict__ proj_b, const float* __restrict__ conv_b,
    const float* __restrict__ ev_w,  const float* __restrict__ ev_b,
    const float* __restrict__ sw_w,  const float* __restrict__ sw_b,
    float* __restrict__ out)
{
    extern __shared__ unsigned char sm[];
    __nv_bfloat16* Bhi = (__nv_bfloat16*)sm;
    __nv_bfloat16* Blo = (__nv_bfloat16*)(sm + BSPL);

    const int tid = threadIdx.x, warp = tid >> 5, lane = tid & 31;
    const int gr = lane >> 2, lc = lane & 3, b = blockIdx.x;
    const int mo = (warp & 7) * 32, to = (warp >> 3) * 64;
    const int mgpair = (warp & 7) * 2;
    const uint32_t sbase = (uint32_t)__cvta_generic_to_shared(sm);
    const int pmb = 2 * (gr & ~1) + (gr & 1);

    int brow[8];
    #pragma unroll
    for (int ni = 0; ni < 8; ni++) brow[ni] = (to + ni * 8 + gr) * SBB;

    // prologue: prefetch steps 0,1 (per-lane own fragments, zero sync)
    issue_step(sbase, 0, mgpair, warp, lane);
    issue_step(sbase, 1, mgpair, warp, lane);

    // zero pad rows 128..131 of both B splits
    for (int i = tid; i < 4 * SBW; i += 512) {
        Bhi[128 * SBW + i] = __float2bfloat16(0.f);
        Blo[128 * SBW + i] = __float2bfloat16(0.f);
    }

    float d[2][8][4];
    #pragma unroll
    for (int mi = 0; mi < 2; mi++)
        #pragma unroll
        for (int ni = 0; ni < 8; ni++)
            #pragma unroll
            for (int r = 0; r < 4; r++) d[mi][ni][r] = 0.f;

    // ======== projection: 4 passes x 16 steps ========
    for (int p = 0; p < 4; p++) {
        __syncthreads();   // prev pass gemm reads done
        {   // build B (permuted pair positions) from x
            int cp = tid & 127, th = tid >> 7;
            int p7 = cp & 7;
            int widx = (cp & ~7) + (p7 < 4 ? 2 * p7 : 2 * (p7 - 4) + 1);
            const float* xp0 = x + ((size_t)b * 1024 + p * 256 + cp * 2) * TLEN;
            const float* xp1 = xp0 + TLEN;
            for (int q = 0; q < 8; q++) {
                int t = th * 32 + q * 4;
                float4 v0 = *(const float4*)(xp0 + t);
                float4 v1 = *(const float4*)(xp1 + t);
                float a0[4] = {v0.x, v0.y, v0.z, v0.w};
                float a1[4] = {v1.x, v1.y, v1.z, v1.w};
                #pragma unroll
                for (int j = 0; j < 4; j++) {
                    __nv_bfloat16 h0, l0, h1, l1;
                    split2(a0[j], h0, l0); split2(a1[j], h1, l1);
                    ((uint32_t*)Bhi)[(t + j) * (SBW / 2) + widx] =
                        (uint32_t)__bfloat16_as_ushort(h0) | ((uint32_t)__bfloat16_as_ushort(h1) << 16);
                    ((uint32_t*)Blo)[(t + j) * (SBW / 2) + widx] =
                        (uint32_t)__bfloat16_as_ushort(l0) | ((uint32_t)__bfloat16_as_ushort(l1) << 16);
                }
            }
        }
        __syncthreads();
        for (int q = 0; q < 16; q++) {
            int s = p * 16 + q;
            wait1();
            const unsigned char* Af = sm + ((s & 1) ? A1_OFF : A0_OFF) + (warp << 11) + (lane << 4);
            gemm16(d, sm, sm + BSPL, Af, brow, q * 32 + lc * 8, 0, 8);
            issue_step(sbase, s + 2, mgpair, warp, lane);
        }
    }
    __syncthreads();
    // proj epilogue: bias, write splits
    {
        float bias[2][2];
        #pragma unroll
        for (int mi = 0; mi < 2; mi++) {
            bias[mi][0] = __ldg(proj_b + mo + mi * 16 + gr);
            bias[mi][1] = __ldg(proj_b + mo + mi * 16 + gr + 8);
        }
        #pragma unroll
        for (int mi = 0; mi < 2; mi++)
            #pragma unroll
            for (int ni = 0; ni < 8; ni++)
                #pragma unroll
                for (int r = 0; r < 4; r++) {
                    int rb = r >> 1;
                    int ms = mo + mi * 16 + pmb + 2 * rb;
                    int t = to + ni * 8 + lc * 2 + (r & 1);
                    float y = d[mi][ni][r] + bias[mi][rb];
                    __nv_bfloat16 hi, lo; split2(y, hi, lo);
                    Bhi[t * SBW + ms] = hi; Blo[t * SBW + ms] = lo;
                }
        __syncthreads();
    }

    // ======== 8 conv layers: 32 steps each ========
    const int DILS[8] = {1, 2, 4, 8, 16, 32, 64, 1};
    for (int l = 0; l < 8; l++) {
        const int D = DILS[l];
        #pragma unroll
        for (int mi = 0; mi < 2; mi++)
            #pragma unroll
            for (int ni = 0; ni < 8; ni++)
                #pragma unroll
                for (int r = 0; r < 4; r++) d[mi][ni][r] = 0.f;

        for (int c = 0; c < 32; c++) {
            int s = 64 + l * 32 + c;
            if (s == NSTEP - 1) wait0(); else wait1();
            int tap = c >> 4, kb = c & 15;
            int shiftB = tap ? D * SBB : 0;
            int nv = 8;
            if (tap && D >= 8) { int nn = (128 - D - to) >> 3; nv = nn < 0 ? 0 : (nn > 8 ? 8 : nn); }
            const unsigned char* Af = sm + ((s & 1) ? A1_OFF : A0_OFF) + (warp << 11) + (lane << 4);
            gemm16(d, sm, sm + BSPL, Af, brow, kb * 32 + lc * 8, shiftB, nv);
            if (s + 2 < NSTEP) issue_step(sbase, s + 2, mgpair, warp, lane);
        }

        // epilogue: bias + leaky + skip + unit-norm
        float* scr = (float*)(sm + SCR_OFF);      // [8][128]
        float* colfac = (float*)(sm + CF_OFF);
        float bias[2][2];
        #pragma unroll
        for (int mi = 0; mi < 2; mi++) {
            bias[mi][0] = __ldg(conv_b + l * HID + mo + mi * 16 + gr);
            bias[mi][1] = __ldg(conv_b + l * HID + mo + mi * 16 + gr + 8);
        }
        float ps[8][2];
        #pragma unroll
        for (int ni = 0; ni < 8; ni++) { ps[ni][0] = 0.f; ps[ni][1] = 0.f; }
        #pragma unroll
        for (int mi = 0; mi < 2; mi++)
            #pragma unroll
            for (int ni = 0; ni < 8; ni++)
                #pragma unroll
                for (int r = 0; r < 4; r++) {
                    int rb = r >> 1;
                    int ms = mo + mi * 16 + pmb + 2 * rb;
                    int t = to + ni * 8 + lc * 2 + (r & 1);
                    float y = d[mi][ni][r] + bias[mi][rb];
                    y = (y > 0.f) ? y : 0.2f * y;
                    y += __bfloat162float(Bhi[t * SBW + ms]) + __bfloat162float(Blo[t * SBW + ms]);
                    d[mi][ni][r] = y;
                    ps[ni][r & 1] = fmaf(y, y, ps[ni][r & 1]);
                }
        #pragma unroll
        for (int ni = 0; ni < 8; ni++)
            #pragma unroll
            for (int j = 0; j < 2; j++) {
                float v = ps[ni][j];
                v += __shfl_down_sync(0xffffffffu, v, 16);
                v += __shfl_down_sync(0xffffffffu, v, 8);
                v += __shfl_down_sync(0xffffffffu, v, 4);
                ps[ni][j] = v;
            }
        if (lane < 4) {
            #pragma unroll
            for (int ni = 0; ni < 8; ni++)
                #pragma unroll
                for (int j = 0; j < 2; j++)
                    scr[(warp & 7) * 128 + to + ni * 8 + lane * 2 + j] = ps[ni][j];
        }
        __syncthreads();
        if (tid < TLEN) {
            float s = 0.f;
            #pragma unroll
            for (int g = 0; g < 8; g++) s += scr[g * 128 + tid];
            colfac[tid] = 1.0f / (sqrtf(s) + 1e-8f);
        }
        __syncthreads();
        float cf[8][2];
        #pragma unroll
        for (int ni = 0; ni < 8; ni++) {
            cf[ni][0] = colfac[to + ni * 8 + lc * 2];
            cf[ni][1] = colfac[to + ni * 8 + lc * 2 + 1];
        }
        #pragma unroll
        for (int mi = 0; mi < 2; mi++)
            #pragma unroll
            for (int ni = 0; ni < 8; ni++)
                #pragma unroll
                for (int r = 0; r < 4; r++) {
                    int rb = r >> 1;
                    int ms = mo + mi * 16 + pmb + 2 * rb;
                    int t = to + ni * 8 + lc * 2 + (r & 1);
                    float y = d[mi][ni][r] * cf[ni][r & 1];
                    __nv_bfloat16 hi, lo; split2(y, hi, lo);
                    Bhi[t * SBW + ms] = hi; Blo[t * SBW + ms] = lo;
                }
        __syncthreads();
    }

    // ======== heads (pipeline fully drained at step 319) ========
    float* pa   = (float*)(sm + A0_OFF);            // [2][17][128] partials
    float* evw  = (float*)(sm + A0_OFF + 17408);    // 16x256 permuted
    float* sww  = evw + CTXD * HID;                 // 256 permuted
    float* evs  = sww + HID;                        // 16x128
    float* attn = evs + CTXD * TLEN;                // 128
    float* redv = (float*)(sm + RV_OFF);
    int*   redi = (int*)(sm + RI_OFF);
    for (int i = tid; i < CTXD * HID; i += 512) {
        int cc = i >> 8, k = i & 255;
        evw[cc * HID + PERMC(k)] = __ldg(ev_w + i);
    }
    if (tid < 256) sww[PERMC(tid)] = __ldg(sw_w + tid);
    __syncthreads();
    if (tid < 256) {
        int t = tid >> 1, hf = tid & 1;
        float a[CTXD + 1];
        #pragma unroll
        for (int cc = 0; cc <= CTXD; cc++) a[cc] = 0.f;
        int i0 = hf * 128;
        for (int i = i0; i < i0 + 128; i++) {
            float hv = __bfloat162float(Bhi[t * SBW + i]) + __bfloat162float(Blo[t * SBW + i]);
            #pragma unroll
            for (int cc = 0; cc < CTXD; cc++) a[cc] = fmaf(evw[cc * HID + i], hv, a[cc]);
            a[CTXD] = fmaf(sww[i], hv, a[CTXD]);
        }
        #pragma unroll
        for (int cc = 0; cc <= CTXD; cc++) pa[(hf * 17 + cc) * 128 + t] = a[cc];
    }
    __syncthreads();
    if (tid < TLEN) {
        #pragma unroll
        for (int cc = 0; cc < CTXD; cc++)
            evs[cc * TLEN + tid] = pa[cc * 128 + tid] + pa[(17 + cc) * 128 + tid] + __ldg(ev_b + cc);
        float sw = pa[16 * 128 + tid] + pa[33 * 128 + tid] + __ldg(sw_b);
        attn[tid] = fmaxf(sw, 0.f);
    }
    __syncthreads();
    if (tid < TLEN) {
        float v = attn[tid]; int idx = tid;
        #pragma unroll
        for (int off = 16; off > 0; off >>= 1) {
            float ov = __shfl_down_sync(0xffffffffu, v, off);
            int   oi = __shfl_down_sync(0xffffffffu, idx, off);
            if (ov > v || (ov == v && oi < idx)) { v = ov; idx = oi; }
        }
        if (lane == 0) { redv[warp] = v; redi[warp] = idx; }
    }
    __syncthreads();
    if (tid == 0) {
        float v = redv[0]; int idx = redi[0];
        for (int w = 1; w < 4; w++)
            if (redv[w] > v || (redv[w] == v && redi[w] < idx)) { v = redv[w]; idx = redi[w]; }
        redv[0] = v; redi[0] = idx;
    }
    __syncthreads();
    const int bi = redi[0]; const float bv = redv[0];
    if (tid < CTXD) out[(size_t)b * CTXD + tid] = evs[tid * TLEN + bi];
    if (tid < TLEN) out[(size_t)gridDim.x * CTXD + (size_t)b * TLEN + tid] = (tid == bi) ? bv : 0.f;
}

extern "C" void kernel_launch(void* const* d_in, const int* in_sizes, int n_in,
                              void* d_out, int out_size)
{
    const float* x      = (const float*)d_in[0];
    const float* proj_w = (const float*)d_in[1];
    const float* proj_b = (const float*)d_in[2];
    const float* conv_w = (const float*)d_in[3];
    const float* conv_b = (const float*)d_in[4];
    const float* ev_w   = (const float*)d_in[5];
    const float* ev_b   = (const float*)d_in[6];
    const float* sw_w   = (const float*)d_in[7];
    const float* sw_b   = (const float*)d_in[8];
    float* out = (float*)d_out;
    const int B = in_sizes[0] / (1024 * TLEN);   // 256

    prep_kernel<<<NSTEP, 256>>>(conv_w, proj_w);
    cudaFuncSetAttribute(Model_26147760898465_kernel,
                         cudaFuncAttributeMaxDynamicSharedMemorySize, SMEM_BYTES);
    Model_26147760898465_kernel<<<B, 512, SMEM_BYTES>>>(
        x, proj_b, conv_b, ev_w, ev_b, sw_w, sw_b, out);
}